// round 3
// baseline (speedup 1.0000x reference)
#include <cuda_runtime.h>
#include <math.h>

#define N_IN   4096
#define N_OUT  1024
#define BATCH  16
#define E_MAX  81920
#define VB_STRIDE (32 * E_MAX)          // per-batch stride in floats

__device__ float g_featT2[N_IN * 512];                       // [n][c*16+b]  8 MB
__device__ float g_Vbuf[(size_t)BATCH * VB_STRIDE];          // [b][m]     168 MB
__device__ int   g_is64;
__device__ int   g_seg[E_MAX];
__device__ int   g_src[E_MAX];

// ---------------- phase -1: dtype detect + index normalize ------------------
// If eval_indices is int64 (little-endian, values < 2^31), every odd 32-bit
// word of the buffer is a zero high-word. If int32, odd words hold src values
// (0..4095, overwhelmingly nonzero across 1024 samples).
__global__ void detect_idx(const int* __restrict__ idx32, int E) {
    __shared__ int any;
    if (threadIdx.x == 0) any = 0;
    __syncthreads();
    int n = min(E, 512);
    int local = 0;
    for (int m = threadIdx.x; m < n; m += 256)
        local |= idx32[4 * m + 1] | idx32[4 * m + 3];
    if (local) atomicOr(&any, 1);
    __syncthreads();
    if (threadIdx.x == 0) g_is64 = any ? 0 : 1;
}

__global__ void convert_idx(const int* __restrict__ idx32, int E) {
    int m = blockIdx.x * 256 + threadIdx.x;
    if (m >= E) return;
    if (g_is64) { g_seg[m] = idx32[4 * m];     g_src[m] = idx32[4 * m + 2]; }
    else        { g_seg[m] = idx32[2 * m];     g_src[m] = idx32[2 * m + 1]; }
}

// ---------------- phase 0: feature permute  feat[b][c][n] -> featT2[n][c*16+b]
__global__ void prep_featT(const float* __restrict__ feat) {
    int i = blockIdx.x * 256 + threadIdx.x;          // over 4096*512
    if (i >= N_IN * 512) return;
    int n  = i >> 9;
    int cb = i & 511;
    int c  = cb >> 4, b = cb & 15;
    g_featT2[i] = feat[(size_t)((b << 5) + c) * N_IN + n];
}

// ---------------- phase A: per-edge filter MLP + apply, writes vals to Vbuf
// block: 512 threads, 32 edges. smem (floats):
//  h1[32][64] @0, h2[32][64] @2048, g[8][16][36] @4096, filt[8][32][36] @8704,
//  locs[64] @17920, goff[1024](int) @17984   -> total 19008 floats (76 KB)
#define SMEM_A_FLOATS 19008

__global__ __launch_bounds__(512, 1) void quad_main(
    const float* __restrict__ W1, const float* __restrict__ W2,
    const float* __restrict__ W3, const float* __restrict__ eval_locs, int E)
{
    extern __shared__ float sm[];
    float* h1_s = sm;
    float* h2_s = sm + 2048;
    float* g_s  = sm + 4096;
    float* f_s  = sm + 8704;
    float* locs = sm + 17920;
    int*   goff = (int*)(sm + 17984);

    const int t   = threadIdx.x;
    const int e0  = blockIdx.x * 32;
    const int net = min(32, E - e0);

    if (t < 2 * net) locs[t] = eval_locs[2 * e0 + t];

    // gather offsets per (e, ci): m = (e0+e)*32+ci ; channel c = m/E, src row m%E
    #pragma unroll
    for (int r = 0; r < 2; r++) {
        int p = t + 512 * r;            // 0..1023
        int e = p >> 5;
        if (e < net) {
            int m  = (e0 + e) * 32 + (p & 31);
            int c  = m / E;
            int rr = m - c * E;
            goff[p] = g_src[rr] * 512 + c * 16;
        }
    }
    __syncthreads();

    // h1[e][j] = sin(loc_e . W1[:,j])
    #pragma unroll
    for (int r = 0; r < 4; r++) {
        int id = t + 512 * r;
        int e = id >> 6, j = id & 63;
        if (e < net)
            h1_s[id] = sinf(locs[2 * e] * W1[j] + locs[2 * e + 1] * W1[64 + j]);
    }
    __syncthreads();

    // h2[e][j] = sin(h1_e . W2[:,j])  (0 for padded edges)
    #pragma unroll
    for (int r = 0; r < 4; r++) {
        int id = t + 512 * r;
        int e = id >> 6, j = id & 63;
        float v = 0.f;
        if (e < net) {
            float s = 0.f;
            #pragma unroll
            for (int k = 0; k < 64; k++)
                s += h1_s[e * 64 + k] * W2[k * 64 + j];
            v = sinf(s);
        }
        h2_s[id] = v;
    }
    __syncthreads();

    // filter gen: thread owns W3 columns {2t, 2t+1} for all 32 edges.
    // Each W3 element is loaded exactly once per block.
    float2 facc[32];
    #pragma unroll
    for (int e = 0; e < 32; e++) facc[e] = make_float2(0.f, 0.f);

    for (int k4 = 0; k4 < 64; k4 += 4) {
        float2 w0 = *(const float2*)&W3[(k4 + 0) * 1024 + 2 * t];
        float2 w1 = *(const float2*)&W3[(k4 + 1) * 1024 + 2 * t];
        float2 w2 = *(const float2*)&W3[(k4 + 2) * 1024 + 2 * t];
        float2 w3 = *(const float2*)&W3[(k4 + 3) * 1024 + 2 * t];
        #pragma unroll
        for (int e = 0; e < 32; e++) {
            float4 h = *(const float4*)&h2_s[e * 64 + k4];
            float ax = facc[e].x, ay = facc[e].y;
            ax += w0.x * h.x; ay += w0.y * h.x;
            ax += w1.x * h.y; ay += w1.y * h.y;
            ax += w2.x * h.z; ay += w2.y * h.z;
            ax += w3.x * h.w; ay += w3.y * h.w;
            facc[e].x = ax; facc[e].y = ay;
        }
    }

    // store/apply mapping
    const int fci = t >> 4;             // col 2t -> ci
    const int fco = (t & 15) * 2;       //        -> co
    const int tt  = t & 127;
    const int ab  = tt >> 3;            // batch
    const int aco = (tt & 7) * 4;       // 4 consecutive co
    const int gid = t >> 7;             // 0..3 -> 2 edges each per sub-phase

    for (int sub = 0; sub < 4; sub++) {
        const int es0 = sub * 8;

        // gather g[e][b][ci] for 8 edges (scrambled per-element offsets)
        #pragma unroll
        for (int r = 0; r < 8; r++) {
            int i  = t + 512 * r;                 // 0..4095
            int p8 = i >> 4;                       // (e,ci) pair 0..255
            int b  = i & 15;
            int e  = p8 >> 5, ci = p8 & 31;
            float v = (es0 + e < net) ? g_featT2[goff[(es0 + e) * 32 + ci] + b] : 0.f;
            g_s[e * 576 + b * 36 + ci] = v;
        }
        // store this sub-phase's filters
        #pragma unroll
        for (int e = 0; e < 8; e++)
            *(float2*)&f_s[e * 1152 + fci * 36 + fco] = facc[es0 + e];
        __syncthreads();

        // apply: vals[b][e][j] = sum_ci g[e][b][ci] * filt[e][ci][j]
        #pragma unroll
        for (int ee = 0; ee < 2; ee++) {
            int e = gid * 2 + ee;
            if (es0 + e < net) {
                const float* gp = &g_s[e * 576 + ab * 36];
                const float* fp = &f_s[e * 1152 + aco];
                float a0 = 0.f, a1 = 0.f, a2 = 0.f, a3 = 0.f;
                #pragma unroll
                for (int ci4 = 0; ci4 < 32; ci4 += 4) {
                    float4 gv = *(const float4*)&gp[ci4];
                    float4 f0 = *(const float4*)&fp[(ci4 + 0) * 36];
                    float4 f1 = *(const float4*)&fp[(ci4 + 1) * 36];
                    float4 f2 = *(const float4*)&fp[(ci4 + 2) * 36];
                    float4 f3 = *(const float4*)&fp[(ci4 + 3) * 36];
                    a0 += gv.x * f0.x + gv.y * f1.x + gv.z * f2.x + gv.w * f3.x;
                    a1 += gv.x * f0.y + gv.y * f1.y + gv.z * f2.y + gv.w * f3.y;
                    a2 += gv.x * f0.z + gv.y * f1.z + gv.z * f2.z + gv.w * f3.z;
                    a3 += gv.x * f0.w + gv.y * f1.w + gv.z * f2.w + gv.w * f3.w;
                }
                size_t m = (size_t)(e0 + es0 + e) * 32 + aco;
                *(float4*)&g_Vbuf[(size_t)ab * VB_STRIDE + m] =
                    make_float4(a0, a1, a2, a3);
            }
        }
        __syncthreads();
    }
}

// ---------------- phase B: out[b][c][o] = sum over seg-range of Vbuf[b][c*E + r]
__global__ __launch_bounds__(512) void quad_scatter(float* __restrict__ out, int E)
{
    const int o = blockIdx.x;
    // contiguous r-range with seg == o (seg sorted, argwhere row-major)
    int lo = 0, hi = E;
    while (lo < hi) { int m = (lo + hi) >> 1; if (g_seg[m] <  o) lo = m + 1; else hi = m; }
    const int r0 = lo;
    hi = E;
    while (lo < hi) { int m = (lo + hi) >> 1; if (g_seg[m] <= o) lo = m + 1; else hi = m; }
    const int r1 = lo;

    const int b = threadIdx.x >> 5;     // warp = batch
    const int l = threadIdx.x & 31;

    for (int c = 0; c < 32; c++) {
        const float* p = &g_Vbuf[(size_t)b * VB_STRIDE + (size_t)c * E];
        float s = 0.f;
        for (int r = r0 + l; r < r1; r += 32) s += p[r];
        #pragma unroll
        for (int d = 16; d; d >>= 1) s += __shfl_xor_sync(0xffffffffu, s, d);
        if (l == 0) out[b * 32768 + c * 1024 + o] = s;
    }
}

extern "C" void kernel_launch(void* const* d_in, const int* in_sizes, int n_in,
                              void* d_out, int out_size) {
    const float* features  = (const float*)d_in[0];
    const float* W1        = (const float*)d_in[1];
    const float* W2        = (const float*)d_in[2];
    const float* W3        = (const float*)d_in[3];
    const float* eval_locs = (const float*)d_in[4];
    const int*   eval_idx  = (const int*)d_in[5];   // int32 OR int64 — detected
    float*       out       = (float*)d_out;

    const int E = in_sizes[4] / 2;   // eval_locs has E*2 floats

    cudaFuncSetAttribute(quad_main, cudaFuncAttributeMaxDynamicSharedMemorySize,
                         SMEM_A_FLOATS * 4);

    detect_idx<<<1, 256>>>(eval_idx, E);
    convert_idx<<<(E + 255) / 256, 256>>>(eval_idx, E);
    prep_featT<<<(N_IN * 512 + 255) / 256, 256>>>(features);
    quad_main<<<(E + 31) / 32, 512, SMEM_A_FLOATS * 4>>>(
        W1, W2, W3, eval_locs, E);
    quad_scatter<<<N_OUT, 512>>>(out, E);
}